// round 6
// baseline (speedup 1.0000x reference)
#include <cuda_runtime.h>

// Ragged segment mean: out[b,d] = mean(seq[b, begin[b]:end[b], d])
// B=2048, L=512, D=512, fp32.
//
// Deterministic work-stealing, single kernel.
// R4 showed balancing raises achieved BW (74.6% -> ~81%) but the scratch
// write + combine kernel ate the gain. Here: persistent 592-CTA grid claims
// whole batches from a self-resetting atomic queue. Each batch is reduced by
// exactly one CTA in fixed order -> bitwise deterministic, zero extra
// traffic, no second kernel.

static constexpr int L_DIM = 512;
static constexpr int D_VEC = 512 / 4;     // 128 float4 per row
static constexpr int NCTA  = 592;         // 4 CTAs/SM on 148 SMs
static constexpr int NTHR  = 128;         // one float4 column per thread

// Work queue. Self-resetting: last CTA to drain restores initial state,
// so every graph replay sees g_next == NCTA, g_done == 0.
__device__ int g_next = NCTA;
__device__ int g_done = 0;

__global__ __launch_bounds__(NTHR) void ragged_mean_ws(
    const float* __restrict__ seq,
    const int*   __restrict__ begin,
    const int*   __restrict__ end,
    float*       __restrict__ out,
    int B)
{
    const int t = threadIdx.x;            // 0..127, float4 column
    __shared__ int s_next;

    int b = blockIdx.x;

    while (b < B) {
        const int s = begin[b];
        const int e = end[b];

        const float4* __restrict__ base =
            reinterpret_cast<const float4*>(seq) + (size_t)b * L_DIM * D_VEC + t;

        float ax = 0.f, ay = 0.f, az = 0.f, aw = 0.f;

        int l = s;
        // 8-deep unroll: 8 independent loads in flight per thread
        for (; l + 8 <= e; l += 8) {
            float4 v0 = base[(size_t)(l + 0) * D_VEC];
            float4 v1 = base[(size_t)(l + 1) * D_VEC];
            float4 v2 = base[(size_t)(l + 2) * D_VEC];
            float4 v3 = base[(size_t)(l + 3) * D_VEC];
            float4 v4 = base[(size_t)(l + 4) * D_VEC];
            float4 v5 = base[(size_t)(l + 5) * D_VEC];
            float4 v6 = base[(size_t)(l + 6) * D_VEC];
            float4 v7 = base[(size_t)(l + 7) * D_VEC];
            ax += v0.x; ay += v0.y; az += v0.z; aw += v0.w;
            ax += v1.x; ay += v1.y; az += v1.z; aw += v1.w;
            ax += v2.x; ay += v2.y; az += v2.z; aw += v2.w;
            ax += v3.x; ay += v3.y; az += v3.z; aw += v3.w;
            ax += v4.x; ay += v4.y; az += v4.z; aw += v4.w;
            ax += v5.x; ay += v5.y; az += v5.z; aw += v5.w;
            ax += v6.x; ay += v6.y; az += v6.z; aw += v6.w;
            ax += v7.x; ay += v7.y; az += v7.z; aw += v7.w;
        }
        for (; l + 2 <= e; l += 2) {
            float4 v0 = base[(size_t)(l + 0) * D_VEC];
            float4 v1 = base[(size_t)(l + 1) * D_VEC];
            ax += v0.x; ay += v0.y; az += v0.z; aw += v0.w;
            ax += v1.x; ay += v1.y; az += v1.z; aw += v1.w;
        }
        if (l < e) {
            float4 v = base[(size_t)l * D_VEC];
            ax += v.x; ay += v.y; az += v.z; aw += v.w;
        }

        const float inv = 1.0f / (float)(e - s);
        float4 r;
        r.x = ax * inv; r.y = ay * inv; r.z = az * inv; r.w = aw * inv;
        reinterpret_cast<float4*>(out)[(size_t)b * D_VEC + t] = r;

        // claim next batch
        if (t == 0) s_next = atomicAdd(&g_next, 1);
        __syncthreads();
        b = s_next;
        __syncthreads();   // protect s_next before next-iteration overwrite
    }

    // Queue reset: last CTA out restores initial state for the next replay.
    if (t == 0) {
        if (atomicAdd(&g_done, 1) == NCTA - 1) {
            g_next = NCTA;
            g_done = 0;
            __threadfence();
        }
    }
}

extern "C" void kernel_launch(void* const* d_in, const int* in_sizes, int n_in,
                              void* d_out, int out_size)
{
    const float* seq   = (const float*)d_in[0];
    const int*   begin = (const int*)d_in[1];
    const int*   end   = (const int*)d_in[2];
    float*       out   = (float*)d_out;

    const int B = in_sizes[1];   // 2048

    ragged_mean_ws<<<NCTA, NTHR>>>(seq, begin, end, out, B);
}

// round 9
// speedup vs baseline: 1.3352x; 1.3352x over previous
#include <cuda_runtime.h>

// Ragged segment mean: out[b,d] = mean(seq[b, begin[b]:end[b], d])
// B=2048, L=512, D=512, fp32.
//
// Split along D. Evidence so far:
//   R1  (2048 CTAs, 1 wave, high occ):        74.6% DRAM (wave-tail imbalance)
//   R4  (8192 CTAs, 3.5 waves, high occ):     ~81%  DRAM (balanced; but scratch+combine ate it)
//   R6  (592 persistent CTAs, 22.8% occ):      58%  DRAM (occupancy-starved)
// This kernel keeps R4's geometry (8192 CTAs, 128 thr, 16 CTAs/SM, 3.5 waves)
// but CTA (b,j) reduces the FULL segment over D-quarter [128j, 128j+128):
// same work-unit size and balance as R4, yet each CTA owns its output slice
// -> no scratch, no combine kernel, minimal traffic.

static constexpr int L_DIM  = 512;
static constexpr int D_VEC  = 512 / 4;    // 128 float4 per full row
static constexpr int Q_VEC  = 32;         // 32 float4 per D-quarter
static constexpr int NTHR   = 128;        // 4 warps: (row-offset, slot)

__global__ __launch_bounds__(NTHR) void ragged_mean_dsplit(
    const float* __restrict__ seq,
    const int*   __restrict__ begin,
    const int*   __restrict__ end,
    float*       __restrict__ out)
{
    const int b = blockIdx.x;
    const int j = blockIdx.y;             // D-quarter 0..3
    const int t = threadIdx.x;
    const int r = t >> 5;                 // row offset within 4-row group, 0..3
    const int c = t & 31;                 // float4 slot within quarter, 0..31

    const int s = begin[b];
    const int e = end[b];

    // float4 pointer to (batch b, quarter j, slot c); row stride = D_VEC
    const float4* __restrict__ base =
        reinterpret_cast<const float4*>(seq)
        + (size_t)b * L_DIM * D_VEC + (size_t)j * Q_VEC + c;

    float ax = 0.f, ay = 0.f, az = 0.f, aw = 0.f;

    // warp w handles rows s+w, s+w+4, s+w+8, ... (each warp reads 512
    // contiguous bytes per row -> fully coalesced 128B lines)
    int l = s + r;
    for (; l + 12 < e; l += 16) {
        float4 v0 = base[(size_t)(l +  0) * D_VEC];
        float4 v1 = base[(size_t)(l +  4) * D_VEC];
        float4 v2 = base[(size_t)(l +  8) * D_VEC];
        float4 v3 = base[(size_t)(l + 12) * D_VEC];
        ax += v0.x; ay += v0.y; az += v0.z; aw += v0.w;
        ax += v1.x; ay += v1.y; az += v1.z; aw += v1.w;
        ax += v2.x; ay += v2.y; az += v2.z; aw += v2.w;
        ax += v3.x; ay += v3.y; az += v3.z; aw += v3.w;
    }
    for (; l < e; l += 4) {
        float4 v = base[(size_t)l * D_VEC];
        ax += v.x; ay += v.y; az += v.z; aw += v.w;
    }

    // cross-warp reduction: 4 partials per slot, fixed order -> deterministic
    __shared__ float4 red[4][Q_VEC];
    red[r][c] = make_float4(ax, ay, az, aw);
    __syncthreads();

    if (r == 0) {
        float4 p0 = red[0][c];
        float4 p1 = red[1][c];
        float4 p2 = red[2][c];
        float4 p3 = red[3][c];
        const float inv = 1.0f / (float)(e - s);
        float4 o;
        o.x = (p0.x + p1.x + p2.x + p3.x) * inv;
        o.y = (p0.y + p1.y + p2.y + p3.y) * inv;
        o.z = (p0.z + p1.z + p2.z + p3.z) * inv;
        o.w = (p0.w + p1.w + p2.w + p3.w) * inv;
        reinterpret_cast<float4*>(out)[(size_t)b * D_VEC + j * Q_VEC + c] = o;
    }
}

extern "C" void kernel_launch(void* const* d_in, const int* in_sizes, int n_in,
                              void* d_out, int out_size)
{
    const float* seq   = (const float*)d_in[0];
    const int*   begin = (const int*)d_in[1];
    const int*   end   = (const int*)d_in[2];
    float*       out   = (float*)d_out;

    const int B = in_sizes[1];   // 2048

    dim3 grid(B, 4);
    ragged_mean_dsplit<<<grid, NTHR>>>(seq, begin, end, out);
}